// round 12
// baseline (speedup 1.0000x reference)
#include <cuda_runtime.h>
#include <cuda_bf16.h>
#include <math.h>
#include <float.h>
#include <stdint.h>

#define MAXN 50000
#define MAXE 800000
#define MAXT (MAXE + MAXN)

// ---------------- scratch (device globals) ----------------
__device__ int   g_deg[MAXN];
__device__ int   g_off[MAXN + 1];
__device__ int   g_cur[MAXN];
__device__ int   g_srcs[MAXT];
__device__ __align__(16) float g_xl[MAXN * 128];
__device__ __align__(16) float g_xr[MAXN * 128];
// bf16 hi/lo split activations, [row][k] row-major, 128 per row
__device__ __align__(16) __nv_bfloat16 g_ah[MAXN * 128];
__device__ __align__(16) __nv_bfloat16 g_al[MAXN * 128];
// transposed + bf16-split weights: [n][k] row-major, 128 bf16 per row
// offsets (elements): Wl1=0 Wr1=16384 Wl2=32768 Wr2=49152 Wl3=65536 Wr3=73728
__device__ __align__(16) __nv_bfloat16 g_wb_hi[81920];
__device__ __align__(16) __nv_bfloat16 g_wb_lo[81920];

// ---------------- helpers ----------------
__device__ __forceinline__ uint32_t pack_bf16_hi(float x, float y, float& rx, float& ry) {
    __nv_bfloat16 hx = __float2bfloat16(x);
    __nv_bfloat16 hy = __float2bfloat16(y);
    rx = x - __bfloat162float(hx);
    ry = y - __bfloat162float(hy);
    return (uint32_t)__bfloat16_as_ushort(hx) | ((uint32_t)__bfloat16_as_ushort(hy) << 16);
}
__device__ __forceinline__ uint32_t pack_bf16(float x, float y) {
    return (uint32_t)__bfloat16_as_ushort(__float2bfloat16(x)) |
           ((uint32_t)__bfloat16_as_ushort(__float2bfloat16(y)) << 16);
}
__device__ __forceinline__ void mma_bf16(float* c, const uint32_t* a, const uint32_t* b) {
    asm volatile(
        "mma.sync.aligned.m16n8k16.row.col.f32.bf16.bf16.f32 "
        "{%0,%1,%2,%3}, {%4,%5,%6,%7}, {%8,%9}, {%0,%1,%2,%3};"
        : "+f"(c[0]), "+f"(c[1]), "+f"(c[2]), "+f"(c[3])
        : "r"(a[0]), "r"(a[1]), "r"(a[2]), "r"(a[3]), "r"(b[0]), "r"(b[1]));
}
__device__ __forceinline__ uint32_t smem_u32(const void* p) {
    uint32_t a;
    asm("{ .reg .u64 t; cvta.to.shared.u64 t, %1; cvt.u32.u64 %0, t; }" : "=r"(a) : "l"(p));
    return a;
}
__device__ __forceinline__ void ldsm_x4(uint32_t* r, uint32_t addr) {
    asm volatile("ldmatrix.sync.aligned.m8n8.x4.shared.b16 {%0,%1,%2,%3}, [%4];"
                 : "=r"(r[0]), "=r"(r[1]), "=r"(r[2]), "=r"(r[3]) : "r"(addr));
}

// ---------------- CSR build ----------------
__global__ void zero_kernel(int n) {
    int i = blockIdx.x * blockDim.x + threadIdx.x;
    if (i < n) g_deg[i] = 0;
}
// 4 edges per thread (int4): E is a multiple of 4 in practice; tail loop guards anyway
__global__ void hist_kernel(const int* __restrict__ ei, int E) {
    int i = (blockIdx.x * blockDim.x + threadIdx.x) * 4;
    if (i + 3 < E) {
        int4 d = *reinterpret_cast<const int4*>(ei + E + i);
        atomicAdd(&g_deg[d.x], 1);
        atomicAdd(&g_deg[d.y], 1);
        atomicAdd(&g_deg[d.z], 1);
        atomicAdd(&g_deg[d.w], 1);
    } else {
        for (int e = i; e < E; ++e) atomicAdd(&g_deg[ei[E + e]], 1);
    }
}
__global__ void scan_kernel(int n) {
    __shared__ int sh[1024];
    int t  = threadIdx.x;
    int cs = (n + 1023) >> 10;
    int b  = t * cs;
    int e  = b + cs; if (e > n) e = n; if (e < b) e = b;
    int s = 0;
    for (int i = b; i < e; ++i) s += g_deg[i] + 1;
    sh[t] = s;
    __syncthreads();
    for (int o = 1; o < 1024; o <<= 1) {
        int add = (t >= o) ? sh[t - o] : 0;
        __syncthreads();
        sh[t] += add;
        __syncthreads();
    }
    int run = sh[t] - s;
    for (int i = b; i < e; ++i) {
        g_off[i] = run; g_cur[i] = run;
        run += g_deg[i] + 1;
    }
    if (t == 1023) g_off[n] = run;
}
// 4 edges per thread; self-loops appended by the last blocks
__global__ void scatter_kernel(const int* __restrict__ ei, int E, int n) {
    int i = (blockIdx.x * blockDim.x + threadIdx.x) * 4;
    if (i + 3 < E) {
        int4 s = *reinterpret_cast<const int4*>(ei + i);
        int4 d = *reinterpret_cast<const int4*>(ei + E + i);
        g_srcs[atomicAdd(&g_cur[d.x], 1)] = s.x;
        g_srcs[atomicAdd(&g_cur[d.y], 1)] = s.y;
        g_srcs[atomicAdd(&g_cur[d.z], 1)] = s.z;
        g_srcs[atomicAdd(&g_cur[d.w], 1)] = s.w;
    } else {
        for (int e = i; e < E && e < i + 4; ++e)
            g_srcs[atomicAdd(&g_cur[ei[E + e]], 1)] = ei[e];
        // self loops: indices E .. E+n-1 mapped onto the same 4-wide grid
        for (int v = i - E; v < i - E + 4; ++v)
            if (v >= 0 && v < n) g_srcs[atomicAdd(&g_cur[v], 1)] = v;
    }
}

// ---------------- weight / activation prep ----------------
__global__ void wprep_kernel(const float* __restrict__ W, int M, int outoff) {
    int idx = blockIdx.x * blockDim.x + threadIdx.x;
    if (idx >= 128 * M) return;
    int nn = idx >> 7;
    int k  = idx & 127;
    float v = W[k * M + nn];
    __nv_bfloat16 h = __float2bfloat16(v);
    __nv_bfloat16 l = __float2bfloat16(v - __bfloat162float(h));
    g_wb_hi[outoff + nn * 128 + k] = h;
    g_wb_lo[outoff + nn * 128 + k] = l;
}
__global__ void aprep_kernel(const float* __restrict__ X, int total4) {
    int i = blockIdx.x * blockDim.x + threadIdx.x;
    if (i >= total4) return;
    float4 v = reinterpret_cast<const float4*>(X)[i];
    float lx, ly, lz, lw;
    uint32_t h0 = pack_bf16_hi(v.x, v.y, lx, ly);
    uint32_t h1 = pack_bf16_hi(v.z, v.w, lz, lw);
    reinterpret_cast<uint2*>(g_ah)[i] = make_uint2(h0, h1);
    reinterpret_cast<uint2*>(g_al)[i] = make_uint2(pack_bf16(lx, ly), pack_bf16(lz, lw));
}

// ---------------- tensor-core GEMM (HMMA + ldmatrix, bf16 hi/lo, 3 chains) — R10-proven ----------------
#define KP 72
template <int BN>
__global__ __launch_bounds__(256, 2) void sgemm_mma(int woffL, int woffR, int n) {
    constexpr int WN  = BN / 2;
    constexpr int TNI = WN / 8;
    constexpr int NP  = TNI / 2;
    int woff4 = ((blockIdx.z == 0) ? woffL : woffR) >> 3;
    float* C  = (blockIdx.z == 0) ? g_xl : g_xr;

    extern __shared__ __align__(16) uint16_t sm[];
    uint16_t* Ah = sm;
    uint16_t* Al = Ah + 128 * KP;
    uint16_t* Wh = Al + 128 * KP;
    uint16_t* Wl = Wh + BN * KP;

    const uint4* gah = reinterpret_cast<const uint4*>(g_ah);
    const uint4* gal = reinterpret_cast<const uint4*>(g_al);
    const uint4* gwh = reinterpret_cast<const uint4*>(g_wb_hi) + woff4;
    const uint4* gwl = reinterpret_cast<const uint4*>(g_wb_lo) + woff4;

    int t    = threadIdx.x;
    int wid  = t >> 5, lane = t & 31;
    int g    = lane >> 2, tg = lane & 3;
    int row0 = blockIdx.y * 128;
    int mw   = wid & 3;
    int nw   = wid >> 2;

    uint32_t sAh = smem_u32(Ah), sAl = smem_u32(Al);
    uint32_t sWh = smem_u32(Wh), sWl = smem_u32(Wl);
    uint32_t aoff = (uint32_t)(((32 * mw + (lane & 15)) * KP + 8 * ((lane >> 4) & 1)) * 2);
    uint32_t boff = (uint32_t)(((WN * nw + 8 * ((lane >> 4) & 1) + (lane & 7)) * KP +
                                8 * ((lane >> 3) & 1)) * 2);

    float acc[2][TNI][4];
    #pragma unroll
    for (int mi = 0; mi < 2; ++mi)
        #pragma unroll
        for (int ni = 0; ni < TNI; ++ni)
            #pragma unroll
            for (int q = 0; q < 4; ++q) acc[mi][ni][q] = 0.f;

    #pragma unroll
    for (int ki = 0; ki < 2; ++ki) {
        #pragma unroll
        for (int j = 0; j < 4; ++j) {
            int c = t + 256 * j;
            int r = c >> 3, o = c & 7;
            int gr = row0 + r; if (gr >= n) gr = 0;
            size_t src = (size_t)gr * 16 + ki * 8 + o;
            *reinterpret_cast<uint4*>(Ah + r * KP + o * 8) = gah[src];
            *reinterpret_cast<uint4*>(Al + r * KP + o * 8) = gal[src];
        }
        constexpr int BC = BN * 8 / 256;
        #pragma unroll
        for (int j = 0; j < BC; ++j) {
            int c = t + 256 * j;
            int r = c >> 3, o = c & 7;
            size_t src = (size_t)r * 16 + ki * 8 + o;
            *reinterpret_cast<uint4*>(Wh + r * KP + o * 8) = gwh[src];
            *reinterpret_cast<uint4*>(Wl + r * KP + o * 8) = gwl[src];
        }
        __syncthreads();

        #pragma unroll
        for (int kk = 0; kk < 4; ++kk) {
            uint32_t kb = (uint32_t)(kk * 16 * 2);
            uint32_t ah[2][4], al[2][4];
            #pragma unroll
            for (int mi = 0; mi < 2; ++mi) {
                uint32_t ao = aoff + (uint32_t)(16 * mi * KP * 2) + kb;
                ldsm_x4(ah[mi], sAh + ao);
                ldsm_x4(al[mi], sAl + ao);
            }
            #pragma unroll
            for (int p = 0; p < NP; ++p) {
                uint32_t bo = boff + (uint32_t)(16 * p * KP * 2) + kb;
                uint32_t bh[4], bl[4];
                ldsm_x4(bh, sWh + bo);
                ldsm_x4(bl, sWl + bo);
                #pragma unroll
                for (int mi = 0; mi < 2; ++mi) {
                    mma_bf16(acc[mi][2 * p],     ah[mi], bh);
                    mma_bf16(acc[mi][2 * p],     ah[mi], bl);
                    mma_bf16(acc[mi][2 * p],     al[mi], bh);
                    mma_bf16(acc[mi][2 * p + 1], ah[mi], bh + 2);
                    mma_bf16(acc[mi][2 * p + 1], ah[mi], bl + 2);
                    mma_bf16(acc[mi][2 * p + 1], al[mi], bh + 2);
                }
            }
        }
        __syncthreads();
    }

    #pragma unroll
    for (int mi = 0; mi < 2; ++mi) {
        int r0 = row0 + 32 * mw + 16 * mi + g;
        #pragma unroll
        for (int ni = 0; ni < TNI; ++ni) {
            int col = WN * nw + 8 * ni + 2 * tg;
            if (r0 < n)
                *reinterpret_cast<float2*>(C + (size_t)r0 * BN + col) =
                    make_float2(acc[mi][ni][0], acc[mi][ni][1]);
            if (r0 + 8 < n)
                *reinterpret_cast<float2*>(C + (size_t)(r0 + 8) * BN + col) =
                    make_float2(acc[mi][ni][2], acc[mi][ni][3]);
        }
    }
}

// ---------------- fused attention, 1-ahead pipelined gather ----------------
template <int F, int C, bool DOELU, bool WB16>
__global__ __launch_bounds__(256) void edge_kernel(
    const float* __restrict__ att, const float* __restrict__ bias,
    float* __restrict__ Cext, int n) {
    constexpr int VPL = F / 32;
    constexpr int GR  = C / VPL;
    int w    = (blockIdx.x * blockDim.x + threadIdx.x) >> 5;
    int lane = threadIdx.x & 31;
    if (w >= n) return;

    float xrv[VPL], av[VPL], bv[VPL];
    if (VPL == 4) {
        float4 t0 = *reinterpret_cast<const float4*>(g_xr + (size_t)w * F + lane * 4);
        xrv[0] = t0.x; xrv[1] = t0.y; xrv[2] = t0.z; xrv[3] = t0.w;
        float4 t1 = *reinterpret_cast<const float4*>(att + lane * 4);
        av[0] = t1.x; av[1] = t1.y; av[2] = t1.z; av[3] = t1.w;
        float4 t2 = *reinterpret_cast<const float4*>(bias + lane * 4);
        bv[0] = t2.x; bv[1] = t2.y; bv[2] = t2.z; bv[3] = t2.w;
    } else {
        float2 t0 = *reinterpret_cast<const float2*>(g_xr + (size_t)w * F + lane * 2);
        xrv[0] = t0.x; xrv[1] = t0.y;
        float2 t1 = *reinterpret_cast<const float2*>(att + lane * 2);
        av[0] = t1.x; av[1] = t1.y;
        float2 t2 = *reinterpret_cast<const float2*>(bias + lane * 2);
        bv[0] = t2.x; bv[1] = t2.y;
    }

    float mh = -INFINITY, ssum = 0.f;
    float acc[VPL];
    #pragma unroll
    for (int j = 0; j < VPL; ++j) acc[j] = 0.f;

    int e0 = g_off[w], e1 = g_off[w + 1];

    // prologue: prefetch first edge (deg >= 1 guaranteed by self-loop)
    float xn[VPL];
    {
        int s = g_srcs[e0];
        if (VPL == 4) {
            float4 u = *reinterpret_cast<const float4*>(g_xl + (size_t)s * F + lane * 4);
            xn[0] = u.x; xn[1] = u.y; xn[2] = u.z; xn[3] = u.w;
        } else {
            float2 u = *reinterpret_cast<const float2*>(g_xl + (size_t)s * F + lane * 2);
            xn[0] = u.x; xn[1] = u.y;
        }
    }
    for (int e = e0; e < e1; ++e) {
        float xv[VPL];
        #pragma unroll
        for (int j = 0; j < VPL; ++j) xv[j] = xn[j];
        if (e + 1 < e1) {                      // issue next gather before compute
            int s = g_srcs[e + 1];
            if (VPL == 4) {
                float4 u = *reinterpret_cast<const float4*>(g_xl + (size_t)s * F + lane * 4);
                xn[0] = u.x; xn[1] = u.y; xn[2] = u.z; xn[3] = u.w;
            } else {
                float2 u = *reinterpret_cast<const float2*>(g_xl + (size_t)s * F + lane * 2);
                xn[0] = u.x; xn[1] = u.y;
            }
        }
        float p = 0.f;
        #pragma unroll
        for (int j = 0; j < VPL; ++j) {
            float m  = xv[j] + xrv[j];
            float lr = (m > 0.f) ? m : 0.2f * m;
            p = fmaf(av[j], lr, p);
        }
        #pragma unroll
        for (int o = 1; o < GR; o <<= 1) p += __shfl_xor_sync(0xffffffffu, p, o);
        float nm    = fmaxf(mh, p);
        float scale = __expf(mh - nm);
        float wgt   = __expf(p - nm);
        ssum = ssum * scale + wgt;
        #pragma unroll
        for (int j = 0; j < VPL; ++j) acc[j] = fmaf(acc[j], scale, wgt * xv[j]);
        mh = nm;
    }
    float inv = 1.f / ssum;
    float o_[VPL];
    #pragma unroll
    for (int j = 0; j < VPL; ++j) {
        float v = fmaf(acc[j], inv, bv[j]);
        if (DOELU) v = (v > 0.f) ? v : expm1f(v);
        o_[j] = v;
    }
    if constexpr (WB16) {
        float r0, r1, r2, r3;
        uint32_t h01 = pack_bf16_hi(o_[0], o_[1], r0, r1);
        uint32_t h23 = pack_bf16_hi(o_[2], o_[3], r2, r3);
        size_t off = (size_t)w * 128 + lane * 4;
        *reinterpret_cast<uint2*>(reinterpret_cast<uint16_t*>(g_ah) + off) = make_uint2(h01, h23);
        *reinterpret_cast<uint2*>(reinterpret_cast<uint16_t*>(g_al) + off) =
            make_uint2(pack_bf16(r0, r1), pack_bf16(r2, r3));
    } else {
        if (VPL == 4) {
            *reinterpret_cast<float4*>(Cext + (size_t)w * F + lane * 4) =
                make_float4(o_[0], o_[1], o_[2], o_[3]);
        } else {
            *reinterpret_cast<float2*>(Cext + (size_t)w * F + lane * 2) =
                make_float2(o_[0], o_[1]);
        }
    }
}

// ---------------- launch ----------------
extern "C" void kernel_launch(void* const* d_in, const int* in_sizes, int n_in,
                              void* d_out, int out_size) {
    const float* x   = (const float*)d_in[0];
    const int*   ei  = (const int*)d_in[1];
    const float* Wl1 = (const float*)d_in[2];
    const float* Wr1 = (const float*)d_in[3];
    const float* a1  = (const float*)d_in[4];
    const float* b1  = (const float*)d_in[5];
    const float* Wl2 = (const float*)d_in[6];
    const float* Wr2 = (const float*)d_in[7];
    const float* a2  = (const float*)d_in[8];
    const float* b2  = (const float*)d_in[9];
    const float* Wl3 = (const float*)d_in[10];
    const float* Wr3 = (const float*)d_in[11];
    const float* a3  = (const float*)d_in[12];
    const float* b3  = (const float*)d_in[13];
    float* out = (float*)d_out;

    int N = in_sizes[0] / 128;
    int E = in_sizes[1] / 2;

    constexpr int SM128 = (128 + 128) * KP * 2 * 2;
    constexpr int SM64  = (128 + 64)  * KP * 2 * 2;
    cudaFuncSetAttribute((const void*)sgemm_mma<128>,
                         cudaFuncAttributeMaxDynamicSharedMemorySize, SM128);
    cudaFuncSetAttribute((const void*)sgemm_mma<64>,
                         cudaFuncAttributeMaxDynamicSharedMemorySize, SM64);

    dim3 gGemm(1, (N + 127) / 128, 2);
    int  eBlocks = (N + 7) / 8;
    int  h4 = (E / 4 + 256) / 256;            // 4-wide hist blocks (covers tail)
    int  s4 = ((E + N) / 4 + 256) / 256;      // 4-wide scatter blocks (covers tail + loops)

    aprep_kernel<<<(N * 32 + 255) / 256, 256>>>(x, N * 32);
    wprep_kernel<<<(128 * 128 + 255) / 256, 256>>>(Wl1, 128, 0);
    wprep_kernel<<<(128 * 128 + 255) / 256, 256>>>(Wr1, 128, 16384);
    sgemm_mma<128><<<gGemm, 256, SM128>>>(0, 16384, N);
    zero_kernel<<<(N + 255) / 256, 256>>>(N);
    hist_kernel<<<h4, 256>>>(ei, E);
    scan_kernel<<<1, 1024>>>(N);
    scatter_kernel<<<s4, 256>>>(ei, E, N);
    wprep_kernel<<<(128 * 128 + 255) / 256, 256>>>(Wl2, 128, 32768);
    wprep_kernel<<<(128 * 128 + 255) / 256, 256>>>(Wr2, 128, 49152);
    wprep_kernel<<<(128 * 64 + 255) / 256, 256>>>(Wl3, 64, 65536);
    wprep_kernel<<<(128 * 64 + 255) / 256, 256>>>(Wr3, 64, 73728);

    edge_kernel<128, 32, true, true><<<eBlocks, 256>>>(a1, b1, nullptr, N);
    sgemm_mma<128><<<gGemm, 256, SM128>>>(32768, 49152, N);
    edge_kernel<128, 32, true, true><<<eBlocks, 256>>>(a2, b2, nullptr, N);
    sgemm_mma<64><<<gGemm, 256, SM64>>>(65536, 73728, N);
    edge_kernel<64, 64, false, false><<<eBlocks, 256>>>(a3, b3, out, N);
}

// round 14
// speedup vs baseline: 1.0277x; 1.0277x over previous
#include <cuda_runtime.h>
#include <cuda_bf16.h>
#include <math.h>
#include <float.h>
#include <stdint.h>

#define MAXN 50000
#define MAXE 800000
#define MAXT (MAXE + MAXN)

// ---------------- scratch (device globals; .bss zero-initialized) ----------------
__device__ int   g_deg[MAXN];          // invariant: zero at kernel_launch entry
__device__ int   g_off[MAXN + 1];
__device__ int   g_cur[MAXN];
__device__ int   g_srcs[MAXT];
__device__ __align__(16) float g_xl[MAXN * 128];
__device__ __align__(16) float g_xr[MAXN * 128];
__device__ __align__(16) __nv_bfloat16 g_ah[MAXN * 128];
__device__ __align__(16) __nv_bfloat16 g_al[MAXN * 128];
// transposed + bf16-split weights: [n][k] row-major, 128 bf16 per row
// offsets (elements): Wl1=0 Wr1=16384 Wl2=32768 Wr2=49152 Wl3=65536 Wr3=73728
__device__ __align__(16) __nv_bfloat16 g_wb_hi[81920];
__device__ __align__(16) __nv_bfloat16 g_wb_lo[81920];

// ---------------- helpers ----------------
__device__ __forceinline__ uint32_t pack_bf16_hi(float x, float y, float& rx, float& ry) {
    __nv_bfloat16 hx = __float2bfloat16(x);
    __nv_bfloat16 hy = __float2bfloat16(y);
    rx = x - __bfloat162float(hx);
    ry = y - __bfloat162float(hy);
    return (uint32_t)__bfloat16_as_ushort(hx) | ((uint32_t)__bfloat16_as_ushort(hy) << 16);
}
__device__ __forceinline__ uint32_t pack_bf16(float x, float y) {
    return (uint32_t)__bfloat16_as_ushort(__float2bfloat16(x)) |
           ((uint32_t)__bfloat16_as_ushort(__float2bfloat16(y)) << 16);
}
__device__ __forceinline__ void mma_bf16(float* c, const uint32_t* a, const uint32_t* b) {
    asm volatile(
        "mma.sync.aligned.m16n8k16.row.col.f32.bf16.bf16.f32 "
        "{%0,%1,%2,%3}, {%4,%5,%6,%7}, {%8,%9}, {%0,%1,%2,%3};"
        : "+f"(c[0]), "+f"(c[1]), "+f"(c[2]), "+f"(c[3])
        : "r"(a[0]), "r"(a[1]), "r"(a[2]), "r"(a[3]), "r"(b[0]), "r"(b[1]));
}
__device__ __forceinline__ uint32_t smem_u32(const void* p) {
    uint32_t a;
    asm("{ .reg .u64 t; cvta.to.shared.u64 t, %1; cvt.u32.u64 %0, t; }" : "=r"(a) : "l"(p));
    return a;
}
__device__ __forceinline__ void ldsm_x4(uint32_t* r, uint32_t addr) {
    asm volatile("ldmatrix.sync.aligned.m8n8.x4.shared.b16 {%0,%1,%2,%3}, [%4];"
                 : "=r"(r[0]), "=r"(r[1]), "=r"(r[2]), "=r"(r[3]) : "r"(addr));
}

// ---------------- CSR build ----------------
// 4 edges per thread (int4)
__global__ void hist_kernel(const int* __restrict__ ei, int E) {
    int i = (blockIdx.x * blockDim.x + threadIdx.x) * 4;
    if (i + 3 < E) {
        int4 d = *reinterpret_cast<const int4*>(ei + E + i);
        atomicAdd(&g_deg[d.x], 1);
        atomicAdd(&g_deg[d.y], 1);
        atomicAdd(&g_deg[d.z], 1);
        atomicAdd(&g_deg[d.w], 1);
    } else {
        for (int e = i; e < E; ++e) atomicAdd(&g_deg[ei[E + e]], 1);
    }
}
// exclusive scan over (deg[i]+1); also RE-ZEROES g_deg for the next invocation
__global__ void scan_kernel(int n) {
    __shared__ int sh[1024];
    int t  = threadIdx.x;
    int cs = (n + 1023) >> 10;
    int b  = t * cs;
    int e  = b + cs; if (e > n) e = n; if (e < b) e = b;
    int s = 0;
    for (int i = b; i < e; ++i) s += g_deg[i] + 1;
    sh[t] = s;
    __syncthreads();
    for (int o = 1; o < 1024; o <<= 1) {
        int add = (t >= o) ? sh[t - o] : 0;
        __syncthreads();
        sh[t] += add;
        __syncthreads();
    }
    int run = sh[t] - s;
    for (int i = b; i < e; ++i) {
        int d = g_deg[i];
        g_off[i] = run; g_cur[i] = run;
        g_deg[i] = 0;                    // restore invariant for next launch/replay
        run += d + 1;
    }
    if (t == 1023) g_off[n] = run;
}
// 4 edges per thread; self-loops handled by the tail range
__global__ void scatter_kernel(const int* __restrict__ ei, int E, int n) {
    int i = (blockIdx.x * blockDim.x + threadIdx.x) * 4;
    if (i + 3 < E) {
        int4 s = *reinterpret_cast<const int4*>(ei + i);
        int4 d = *reinterpret_cast<const int4*>(ei + E + i);
        g_srcs[atomicAdd(&g_cur[d.x], 1)] = s.x;
        g_srcs[atomicAdd(&g_cur[d.y], 1)] = s.y;
        g_srcs[atomicAdd(&g_cur[d.z], 1)] = s.z;
        g_srcs[atomicAdd(&g_cur[d.w], 1)] = s.w;
    } else {
        for (int e = i; e < E && e < i + 4; ++e)
            g_srcs[atomicAdd(&g_cur[ei[E + e]], 1)] = ei[e];
        for (int v = i - E; v < i - E + 4; ++v)
            if (v >= 0 && v < n) g_srcs[atomicAdd(&g_cur[v], 1)] = v;
    }
}

// ---------------- prep ----------------
// all 6 weights in one launch; segments: 4x16384 (M=128) + 2x8192 (M=64)
__global__ void wprep_all(const float* __restrict__ Wl1, const float* __restrict__ Wr1,
                          const float* __restrict__ Wl2, const float* __restrict__ Wr2,
                          const float* __restrict__ Wl3, const float* __restrict__ Wr3) {
    int idx = blockIdx.x * blockDim.x + threadIdx.x;
    if (idx >= 81920) return;
    const float* W;
    int M, local, off;
    if (idx < 65536) {
        int w = idx >> 14; local = idx & 16383; M = 128; off = w << 14;
        W = (w == 0) ? Wl1 : (w == 1) ? Wr1 : (w == 2) ? Wl2 : Wr2;
    } else {
        int j = idx - 65536;
        int w = j >> 13; local = j & 8191; M = 64; off = 65536 + (w << 13);
        W = w ? Wr3 : Wl3;
    }
    int nn = local >> 7, k = local & 127;
    float v = W[k * M + nn];
    __nv_bfloat16 h = __float2bfloat16(v);
    __nv_bfloat16 l = __float2bfloat16(v - __bfloat162float(h));
    g_wb_hi[off + local] = h;
    g_wb_lo[off + local] = l;
}
__global__ void aprep_kernel(const float* __restrict__ X, int total4) {
    int i = blockIdx.x * blockDim.x + threadIdx.x;
    if (i >= total4) return;
    float4 v = reinterpret_cast<const float4*>(X)[i];
    float lx, ly, lz, lw;
    uint32_t h0 = pack_bf16_hi(v.x, v.y, lx, ly);
    uint32_t h1 = pack_bf16_hi(v.z, v.w, lz, lw);
    reinterpret_cast<uint2*>(g_ah)[i] = make_uint2(h0, h1);
    reinterpret_cast<uint2*>(g_al)[i] = make_uint2(pack_bf16(lx, ly), pack_bf16(lz, lw));
}

// ---------------- tensor-core GEMM (HMMA + ldmatrix, bf16 hi/lo, 3 chains) — R10-proven ----------------
#define KP 72
template <int BN>
__global__ __launch_bounds__(256, 2) void sgemm_mma(int woffL, int woffR, int n) {
    constexpr int WN  = BN / 2;
    constexpr int TNI = WN / 8;
    constexpr int NP  = TNI / 2;
    int woff4 = ((blockIdx.z == 0) ? woffL : woffR) >> 3;
    float* C  = (blockIdx.z == 0) ? g_xl : g_xr;

    extern __shared__ __align__(16) uint16_t sm[];
    uint16_t* Ah = sm;
    uint16_t* Al = Ah + 128 * KP;
    uint16_t* Wh = Al + 128 * KP;
    uint16_t* Wl = Wh + BN * KP;

    const uint4* gah = reinterpret_cast<const uint4*>(g_ah);
    const uint4* gal = reinterpret_cast<const uint4*>(g_al);
    const uint4* gwh = reinterpret_cast<const uint4*>(g_wb_hi) + woff4;
    const uint4* gwl = reinterpret_cast<const uint4*>(g_wb_lo) + woff4;

    int t    = threadIdx.x;
    int wid  = t >> 5, lane = t & 31;
    int g    = lane >> 2, tg = lane & 3;
    int row0 = blockIdx.y * 128;
    int mw   = wid & 3;
    int nw   = wid >> 2;

    uint32_t sAh = smem_u32(Ah), sAl = smem_u32(Al);
    uint32_t sWh = smem_u32(Wh), sWl = smem_u32(Wl);
    uint32_t aoff = (uint32_t)(((32 * mw + (lane & 15)) * KP + 8 * ((lane >> 4) & 1)) * 2);
    uint32_t boff = (uint32_t)(((WN * nw + 8 * ((lane >> 4) & 1) + (lane & 7)) * KP +
                                8 * ((lane >> 3) & 1)) * 2);

    float acc[2][TNI][4];
    #pragma unroll
    for (int mi = 0; mi < 2; ++mi)
        #pragma unroll
        for (int ni = 0; ni < TNI; ++ni)
            #pragma unroll
            for (int q = 0; q < 4; ++q) acc[mi][ni][q] = 0.f;

    #pragma unroll
    for (int ki = 0; ki < 2; ++ki) {
        #pragma unroll
        for (int j = 0; j < 4; ++j) {
            int c = t + 256 * j;
            int r = c >> 3, o = c & 7;
            int gr = row0 + r; if (gr >= n) gr = 0;
            size_t src = (size_t)gr * 16 + ki * 8 + o;
            *reinterpret_cast<uint4*>(Ah + r * KP + o * 8) = gah[src];
            *reinterpret_cast<uint4*>(Al + r * KP + o * 8) = gal[src];
        }
        constexpr int BC = BN * 8 / 256;
        #pragma unroll
        for (int j = 0; j < BC; ++j) {
            int c = t + 256 * j;
            int r = c >> 3, o = c & 7;
            size_t src = (size_t)r * 16 + ki * 8 + o;
            *reinterpret_cast<uint4*>(Wh + r * KP + o * 8) = gwh[src];
            *reinterpret_cast<uint4*>(Wl + r * KP + o * 8) = gwl[src];
        }
        __syncthreads();

        #pragma unroll
        for (int kk = 0; kk < 4; ++kk) {
            uint32_t kb = (uint32_t)(kk * 16 * 2);
            uint32_t ah[2][4], al[2][4];
            #pragma unroll
            for (int mi = 0; mi < 2; ++mi) {
                uint32_t ao = aoff + (uint32_t)(16 * mi * KP * 2) + kb;
                ldsm_x4(ah[mi], sAh + ao);
                ldsm_x4(al[mi], sAl + ao);
            }
            #pragma unroll
            for (int p = 0; p < NP; ++p) {
                uint32_t bo = boff + (uint32_t)(16 * p * KP * 2) + kb;
                uint32_t bh[4], bl[4];
                ldsm_x4(bh, sWh + bo);
                ldsm_x4(bl, sWl + bo);
                #pragma unroll
                for (int mi = 0; mi < 2; ++mi) {
                    mma_bf16(acc[mi][2 * p],     ah[mi], bh);
                    mma_bf16(acc[mi][2 * p],     ah[mi], bl);
                    mma_bf16(acc[mi][2 * p],     al[mi], bh);
                    mma_bf16(acc[mi][2 * p + 1], ah[mi], bh + 2);
                    mma_bf16(acc[mi][2 * p + 1], ah[mi], bl + 2);
                    mma_bf16(acc[mi][2 * p + 1], al[mi], bh + 2);
                }
            }
        }
        __syncthreads();
    }

    #pragma unroll
    for (int mi = 0; mi < 2; ++mi) {
        int r0 = row0 + 32 * mw + 16 * mi + g;
        #pragma unroll
        for (int ni = 0; ni < TNI; ++ni) {
            int col = WN * nw + 8 * ni + 2 * tg;
            if (r0 < n)
                *reinterpret_cast<float2*>(C + (size_t)r0 * BN + col) =
                    make_float2(acc[mi][ni][0], acc[mi][ni][1]);
            if (r0 + 8 < n)
                *reinterpret_cast<float2*>(C + (size_t)(r0 + 8) * BN + col) =
                    make_float2(acc[mi][ni][2], acc[mi][ni][3]);
        }
    }
}

// ---------------- fused attention + online softmax + aggregate (R10-proven, no pipeline) ----------------
template <int F, int C, bool DOELU, bool WB16>
__global__ __launch_bounds__(256) void edge_kernel(
    const float* __restrict__ att, const float* __restrict__ bias,
    float* __restrict__ Cext, int n) {
    constexpr int VPL = F / 32;
    constexpr int GR  = C / VPL;
    int w    = (blockIdx.x * blockDim.x + threadIdx.x) >> 5;
    int lane = threadIdx.x & 31;
    if (w >= n) return;

    float xrv[VPL], av[VPL], bv[VPL];
    if (VPL == 4) {
        float4 t0 = *reinterpret_cast<const float4*>(g_xr + (size_t)w * F + lane * 4);
        xrv[0] = t0.x; xrv[1] = t0.y; xrv[2] = t0.z; xrv[3] = t0.w;
        float4 t1 = *reinterpret_cast<const float4*>(att + lane * 4);
        av[0] = t1.x; av[1] = t1.y; av[2] = t1.z; av[3] = t1.w;
        float4 t2 = *reinterpret_cast<const float4*>(bias + lane * 4);
        bv[0] = t2.x; bv[1] = t2.y; bv[2] = t2.z; bv[3] = t2.w;
    } else {
        float2 t0 = *reinterpret_cast<const float2*>(g_xr + (size_t)w * F + lane * 2);
        xrv[0] = t0.x; xrv[1] = t0.y;
        float2 t1 = *reinterpret_cast<const float2*>(att + lane * 2);
        av[0] = t1.x; av[1] = t1.y;
        float2 t2 = *reinterpret_cast<const float2*>(bias + lane * 2);
        bv[0] = t2.x; bv[1] = t2.y;
    }

    float mh = -INFINITY, ssum = 0.f;
    float acc[VPL];
    #pragma unroll
    for (int j = 0; j < VPL; ++j) acc[j] = 0.f;

    int e0 = g_off[w], e1 = g_off[w + 1];
    for (int e = e0; e < e1; ++e) {
        int s = g_srcs[e];
        float xv[VPL];
        if (VPL == 4) {
            float4 t = *reinterpret_cast<const float4*>(g_xl + (size_t)s * F + lane * 4);
            xv[0] = t.x; xv[1] = t.y; xv[2] = t.z; xv[3] = t.w;
        } else {
            float2 t = *reinterpret_cast<const float2*>(g_xl + (size_t)s * F + lane * 2);
            xv[0] = t.x; xv[1] = t.y;
        }
        float p = 0.f;
        #pragma unroll
        for (int j = 0; j < VPL; ++j) {
            float m  = xv[j] + xrv[j];
            float lr = (m > 0.f) ? m : 0.2f * m;
            p = fmaf(av[j], lr, p);
        }
        #pragma unroll
        for (int o = 1; o < GR; o <<= 1) p += __shfl_xor_sync(0xffffffffu, p, o);
        float nm    = fmaxf(mh, p);
        float scale = __expf(mh - nm);
        float wgt   = __expf(p - nm);
        ssum = ssum * scale + wgt;
        #pragma unroll
        for (int j = 0; j < VPL; ++j) acc[j] = fmaf(acc[j], scale, wgt * xv[j]);
        mh = nm;
    }
    float inv = 1.f / ssum;
    float o_[VPL];
    #pragma unroll
    for (int j = 0; j < VPL; ++j) {
        float v = fmaf(acc[j], inv, bv[j]);
        if (DOELU) v = (v > 0.f) ? v : expm1f(v);
        o_[j] = v;
    }
    if constexpr (WB16) {
        float r0, r1, r2, r3;
        uint32_t h01 = pack_bf16_hi(o_[0], o_[1], r0, r1);
        uint32_t h23 = pack_bf16_hi(o_[2], o_[3], r2, r3);
        size_t off = (size_t)w * 128 + lane * 4;
        *reinterpret_cast<uint2*>(reinterpret_cast<uint16_t*>(g_ah) + off) = make_uint2(h01, h23);
        *reinterpret_cast<uint2*>(reinterpret_cast<uint16_t*>(g_al) + off) =
            make_uint2(pack_bf16(r0, r1), pack_bf16(r2, r3));
    } else {
        if (VPL == 4) {
            *reinterpret_cast<float4*>(Cext + (size_t)w * F + lane * 4) =
                make_float4(o_[0], o_[1], o_[2], o_[3]);
        } else {
            *reinterpret_cast<float2*>(Cext + (size_t)w * F + lane * 2) =
                make_float2(o_[0], o_[1]);
        }
    }
}

// ---------------- launch (11 graph nodes) ----------------
extern "C" void kernel_launch(void* const* d_in, const int* in_sizes, int n_in,
                              void* d_out, int out_size) {
    const float* x   = (const float*)d_in[0];
    const int*   ei  = (const int*)d_in[1];
    const float* Wl1 = (const float*)d_in[2];
    const float* Wr1 = (const float*)d_in[3];
    const float* a1  = (const float*)d_in[4];
    const float* b1  = (const float*)d_in[5];
    const float* Wl2 = (const float*)d_in[6];
    const float* Wr2 = (const float*)d_in[7];
    const float* a2  = (const float*)d_in[8];
    const float* b2  = (const float*)d_in[9];
    const float* Wl3 = (const float*)d_in[10];
    const float* Wr3 = (const float*)d_in[11];
    const float* a3  = (const float*)d_in[12];
    const float* b3  = (const float*)d_in[13];
    float* out = (float*)d_out;

    int N = in_sizes[0] / 128;
    int E = in_sizes[1] / 2;

    constexpr int SM128 = (128 + 128) * KP * 2 * 2;
    constexpr int SM64  = (128 + 64)  * KP * 2 * 2;
    cudaFuncSetAttribute((const void*)sgemm_mma<128>,
                         cudaFuncAttributeMaxDynamicSharedMemorySize, SM128);
    cudaFuncSetAttribute((const void*)sgemm_mma<64>,
                         cudaFuncAttributeMaxDynamicSharedMemorySize, SM64);

    dim3 gGemm(1, (N + 127) / 128, 2);
    int  eBlocks = (N + 7) / 8;
    int  h4 = (E / 4 + 256) / 256;
    int  s4 = ((E + N) / 4 + 256) / 256;

    aprep_kernel<<<(N * 32 + 255) / 256, 256>>>(x, N * 32);                    // 1
    wprep_all<<<(81920 + 255) / 256, 256>>>(Wl1, Wr1, Wl2, Wr2, Wl3, Wr3);     // 2
    hist_kernel<<<h4, 256>>>(ei, E);                                           // 3 (deg==0 invariant)
    sgemm_mma<128><<<gGemm, 256, SM128>>>(0, 16384, N);                        // 4 <- profile slot
    scan_kernel<<<1, 1024>>>(N);                                               // 5 (re-zeroes deg)
    scatter_kernel<<<s4, 256>>>(ei, E, N);                                     // 6
    edge_kernel<128, 32, true, true><<<eBlocks, 256>>>(a1, b1, nullptr, N);    // 7
    sgemm_mma<128><<<gGemm, 256, SM128>>>(32768, 49152, N);                    // 8
    edge_kernel<128, 32, true, true><<<eBlocks, 256>>>(a2, b2, nullptr, N);    // 9
    sgemm_mma<64><<<gGemm, 256, SM64>>>(65536, 73728, N);                      // 10
    edge_kernel<64, 64, false, false><<<eBlocks, 256>>>(a3, b3, out, N);       // 11
}

// round 16
// speedup vs baseline: 1.1248x; 1.0944x over previous
#include <cuda_runtime.h>
#include <cuda_bf16.h>
#include <math.h>
#include <float.h>
#include <stdint.h>

#define MAXN 50000
#define MAXE 800000
#define MAXT (MAXE + MAXN)

// ---------------- scratch (device globals; .bss zero-initialized) ----------------
__device__ int   g_deg[MAXN];          // invariant: zero at kernel_launch entry
__device__ int   g_off[MAXN + 1];
__device__ int   g_cur[MAXN];
__device__ int   g_srcs[MAXT];
__device__ __align__(16) float g_xl[MAXN * 128];
__device__ __align__(16) float g_xr[MAXN * 128];
__device__ __align__(16) __nv_bfloat16 g_ah[MAXN * 128];
__device__ __align__(16) __nv_bfloat16 g_al[MAXN * 128];
// transposed + bf16-split weights: [n][k] row-major, 128 bf16 per row
// offsets (elements): Wl1=0 Wr1=16384 Wl2=32768 Wr2=49152 Wl3=65536 Wr3=73728
__device__ __align__(16) __nv_bfloat16 g_wb_hi[81920];
__device__ __align__(16) __nv_bfloat16 g_wb_lo[81920];

// ---------------- helpers ----------------
__device__ __forceinline__ uint32_t pack_bf16_hi(float x, float y, float& rx, float& ry) {
    __nv_bfloat16 hx = __float2bfloat16(x);
    __nv_bfloat16 hy = __float2bfloat16(y);
    rx = x - __bfloat162float(hx);
    ry = y - __bfloat162float(hy);
    return (uint32_t)__bfloat16_as_ushort(hx) | ((uint32_t)__bfloat16_as_ushort(hy) << 16);
}
__device__ __forceinline__ uint32_t pack_bf16(float x, float y) {
    return (uint32_t)__bfloat16_as_ushort(__float2bfloat16(x)) |
           ((uint32_t)__bfloat16_as_ushort(__float2bfloat16(y)) << 16);
}
__device__ __forceinline__ void mma_bf16(float* c, const uint32_t* a, const uint32_t* b) {
    asm volatile(
        "mma.sync.aligned.m16n8k16.row.col.f32.bf16.bf16.f32 "
        "{%0,%1,%2,%3}, {%4,%5,%6,%7}, {%8,%9}, {%0,%1,%2,%3};"
        : "+f"(c[0]), "+f"(c[1]), "+f"(c[2]), "+f"(c[3])
        : "r"(a[0]), "r"(a[1]), "r"(a[2]), "r"(a[3]), "r"(b[0]), "r"(b[1]));
}
__device__ __forceinline__ uint32_t smem_u32(const void* p) {
    uint32_t a;
    asm("{ .reg .u64 t; cvta.to.shared.u64 t, %1; cvt.u32.u64 %0, t; }" : "=r"(a) : "l"(p));
    return a;
}
__device__ __forceinline__ void ldsm_x4(uint32_t* r, uint32_t addr) {
    asm volatile("ldmatrix.sync.aligned.m8n8.x4.shared.b16 {%0,%1,%2,%3}, [%4];"
                 : "=r"(r[0]), "=r"(r[1]), "=r"(r[2]), "=r"(r[3]) : "r"(addr));
}

// ---------------- CSR build ----------------
__global__ void hist_kernel(const int* __restrict__ ei, int E) {
    int i = (blockIdx.x * blockDim.x + threadIdx.x) * 4;
    if (i + 3 < E) {
        int4 d = *reinterpret_cast<const int4*>(ei + E + i);
        atomicAdd(&g_deg[d.x], 1);
        atomicAdd(&g_deg[d.y], 1);
        atomicAdd(&g_deg[d.z], 1);
        atomicAdd(&g_deg[d.w], 1);
    } else {
        for (int e = i; e < E; ++e) atomicAdd(&g_deg[ei[E + e]], 1);
    }
}
// exclusive scan over (deg[i]+1); also RE-ZEROES g_deg for the next invocation
__global__ void scan_kernel(int n) {
    __shared__ int sh[1024];
    int t  = threadIdx.x;
    int cs = (n + 1023) >> 10;
    int b  = t * cs;
    int e  = b + cs; if (e > n) e = n; if (e < b) e = b;
    int s = 0;
    for (int i = b; i < e; ++i) s += g_deg[i] + 1;
    sh[t] = s;
    __syncthreads();
    for (int o = 1; o < 1024; o <<= 1) {
        int add = (t >= o) ? sh[t - o] : 0;
        __syncthreads();
        sh[t] += add;
        __syncthreads();
    }
    int run = sh[t] - s;
    for (int i = b; i < e; ++i) {
        int d = g_deg[i];
        g_off[i] = run; g_cur[i] = run;
        g_deg[i] = 0;
        run += d + 1;
    }
    if (t == 1023) g_off[n] = run;
}
__global__ void scatter_kernel(const int* __restrict__ ei, int E, int n) {
    int i = (blockIdx.x * blockDim.x + threadIdx.x) * 4;
    if (i + 3 < E) {
        int4 s = *reinterpret_cast<const int4*>(ei + i);
        int4 d = *reinterpret_cast<const int4*>(ei + E + i);
        g_srcs[atomicAdd(&g_cur[d.x], 1)] = s.x;
        g_srcs[atomicAdd(&g_cur[d.y], 1)] = s.y;
        g_srcs[atomicAdd(&g_cur[d.z], 1)] = s.z;
        g_srcs[atomicAdd(&g_cur[d.w], 1)] = s.w;
    } else {
        for (int e = i; e < E && e < i + 4; ++e)
            g_srcs[atomicAdd(&g_cur[ei[E + e]], 1)] = ei[e];
        for (int v = i - E; v < i - E + 4; ++v)
            if (v >= 0 && v < n) g_srcs[atomicAdd(&g_cur[v], 1)] = v;
    }
}

// ---------------- prep ----------------
__global__ void wprep_all(const float* __restrict__ Wl1, const float* __restrict__ Wr1,
                          const float* __restrict__ Wl2, const float* __restrict__ Wr2,
                          const float* __restrict__ Wl3, const float* __restrict__ Wr3) {
    int idx = blockIdx.x * blockDim.x + threadIdx.x;
    if (idx >= 81920) return;
    const float* W;
    int M, local, off;
    if (idx < 65536) {
        int w = idx >> 14; local = idx & 16383; M = 128; off = w << 14;
        W = (w == 0) ? Wl1 : (w == 1) ? Wr1 : (w == 2) ? Wl2 : Wr2;
    } else {
        int j = idx - 65536;
        int w = j >> 13; local = j & 8191; M = 64; off = 65536 + (w << 13);
        W = w ? Wr3 : Wl3;
    }
    int nn = local >> 7, k = local & 127;
    float v = W[k * M + nn];
    __nv_bfloat16 h = __float2bfloat16(v);
    __nv_bfloat16 l = __float2bfloat16(v - __bfloat162float(h));
    g_wb_hi[off + local] = h;
    g_wb_lo[off + local] = l;
}
__global__ void aprep_kernel(const float* __restrict__ X, int total4) {
    int i = blockIdx.x * blockDim.x + threadIdx.x;
    if (i >= total4) return;
    float4 v = reinterpret_cast<const float4*>(X)[i];
    float lx, ly, lz, lw;
    uint32_t h0 = pack_bf16_hi(v.x, v.y, lx, ly);
    uint32_t h1 = pack_bf16_hi(v.z, v.w, lz, lw);
    reinterpret_cast<uint2*>(g_ah)[i] = make_uint2(h0, h1);
    reinterpret_cast<uint2*>(g_al)[i] = make_uint2(pack_bf16(lx, ly), pack_bf16(lz, lw));
}

// ---------------- tensor-core GEMM (HMMA + ldmatrix, bf16 hi/lo, 3 chains) — R10-proven ----------------
#define KP 72
template <int BN>
__global__ __launch_bounds__(256, 2) void sgemm_mma(int woffL, int woffR, int n) {
    constexpr int WN  = BN / 2;
    constexpr int TNI = WN / 8;
    constexpr int NP  = TNI / 2;
    int woff4 = ((blockIdx.z == 0) ? woffL : woffR) >> 3;
    float* C  = (blockIdx.z == 0) ? g_xl : g_xr;

    extern __shared__ __align__(16) uint16_t sm[];
    uint16_t* Ah = sm;
    uint16_t* Al = Ah + 128 * KP;
    uint16_t* Wh = Al + 128 * KP;
    uint16_t* Wl = Wh + BN * KP;

    const uint4* gah = reinterpret_cast<const uint4*>(g_ah);
    const uint4* gal = reinterpret_cast<const uint4*>(g_al);
    const uint4* gwh = reinterpret_cast<const uint4*>(g_wb_hi) + woff4;
    const uint4* gwl = reinterpret_cast<const uint4*>(g_wb_lo) + woff4;

    int t    = threadIdx.x;
    int wid  = t >> 5, lane = t & 31;
    int g    = lane >> 2, tg = lane & 3;
    int row0 = blockIdx.y * 128;
    int mw   = wid & 3;
    int nw   = wid >> 2;

    uint32_t sAh = smem_u32(Ah), sAl = smem_u32(Al);
    uint32_t sWh = smem_u32(Wh), sWl = smem_u32(Wl);
    uint32_t aoff = (uint32_t)(((32 * mw + (lane & 15)) * KP + 8 * ((lane >> 4) & 1)) * 2);
    uint32_t boff = (uint32_t)(((WN * nw + 8 * ((lane >> 4) & 1) + (lane & 7)) * KP +
                                8 * ((lane >> 3) & 1)) * 2);

    float acc[2][TNI][4];
    #pragma unroll
    for (int mi = 0; mi < 2; ++mi)
        #pragma unroll
        for (int ni = 0; ni < TNI; ++ni)
            #pragma unroll
            for (int q = 0; q < 4; ++q) acc[mi][ni][q] = 0.f;

    #pragma unroll
    for (int ki = 0; ki < 2; ++ki) {
        #pragma unroll
        for (int j = 0; j < 4; ++j) {
            int c = t + 256 * j;
            int r = c >> 3, o = c & 7;
            int gr = row0 + r; if (gr >= n) gr = 0;
            size_t src = (size_t)gr * 16 + ki * 8 + o;
            *reinterpret_cast<uint4*>(Ah + r * KP + o * 8) = gah[src];
            *reinterpret_cast<uint4*>(Al + r * KP + o * 8) = gal[src];
        }
        constexpr int BC = BN * 8 / 256;
        #pragma unroll
        for (int j = 0; j < BC; ++j) {
            int c = t + 256 * j;
            int r = c >> 3, o = c & 7;
            size_t src = (size_t)r * 16 + ki * 8 + o;
            *reinterpret_cast<uint4*>(Wh + r * KP + o * 8) = gwh[src];
            *reinterpret_cast<uint4*>(Wl + r * KP + o * 8) = gwl[src];
        }
        __syncthreads();

        #pragma unroll
        for (int kk = 0; kk < 4; ++kk) {
            uint32_t kb = (uint32_t)(kk * 16 * 2);
            uint32_t ah[2][4], al[2][4];
            #pragma unroll
            for (int mi = 0; mi < 2; ++mi) {
                uint32_t ao = aoff + (uint32_t)(16 * mi * KP * 2) + kb;
                ldsm_x4(ah[mi], sAh + ao);
                ldsm_x4(al[mi], sAl + ao);
            }
            #pragma unroll
            for (int p = 0; p < NP; ++p) {
                uint32_t bo = boff + (uint32_t)(16 * p * KP * 2) + kb;
                uint32_t bh[4], bl[4];
                ldsm_x4(bh, sWh + bo);
                ldsm_x4(bl, sWl + bo);
                #pragma unroll
                for (int mi = 0; mi < 2; ++mi) {
                    mma_bf16(acc[mi][2 * p],     ah[mi], bh);
                    mma_bf16(acc[mi][2 * p],     ah[mi], bl);
                    mma_bf16(acc[mi][2 * p],     al[mi], bh);
                    mma_bf16(acc[mi][2 * p + 1], ah[mi], bh + 2);
                    mma_bf16(acc[mi][2 * p + 1], ah[mi], bl + 2);
                    mma_bf16(acc[mi][2 * p + 1], al[mi], bh + 2);
                }
            }
        }
        __syncthreads();
    }

    #pragma unroll
    for (int mi = 0; mi < 2; ++mi) {
        int r0 = row0 + 32 * mw + 16 * mi + g;
        #pragma unroll
        for (int ni = 0; ni < TNI; ++ni) {
            int col = WN * nw + 8 * ni + 2 * tg;
            if (r0 < n)
                *reinterpret_cast<float2*>(C + (size_t)r0 * BN + col) =
                    make_float2(acc[mi][ni][0], acc[mi][ni][1]);
            if (r0 + 8 < n)
                *reinterpret_cast<float2*>(C + (size_t)(r0 + 8) * BN + col) =
                    make_float2(acc[mi][ni][2], acc[mi][ni][3]);
        }
    }
}

// ---------------- fused attention + online softmax + aggregate (R10-proven) ----------------
template <int F, int C, bool DOELU, bool WB16>
__global__ __launch_bounds__(256) void edge_kernel(
    const float* __restrict__ att, const float* __restrict__ bias,
    float* __restrict__ Cext, int n) {
    constexpr int VPL = F / 32;
    constexpr int GR  = C / VPL;
    int w    = (blockIdx.x * blockDim.x + threadIdx.x) >> 5;
    int lane = threadIdx.x & 31;
    if (w >= n) return;

    float xrv[VPL], av[VPL], bv[VPL];
    if (VPL == 4) {
        float4 t0 = *reinterpret_cast<const float4*>(g_xr + (size_t)w * F + lane * 4);
        xrv[0] = t0.x; xrv[1] = t0.y; xrv[2] = t0.z; xrv[3] = t0.w;
        float4 t1 = *reinterpret_cast<const float4*>(att + lane * 4);
        av[0] = t1.x; av[1] = t1.y; av[2] = t1.z; av[3] = t1.w;
        float4 t2 = *reinterpret_cast<const float4*>(bias + lane * 4);
        bv[0] = t2.x; bv[1] = t2.y; bv[2] = t2.z; bv[3] = t2.w;
    } else {
        float2 t0 = *reinterpret_cast<const float2*>(g_xr + (size_t)w * F + lane * 2);
        xrv[0] = t0.x; xrv[1] = t0.y;
        float2 t1 = *reinterpret_cast<const float2*>(att + lane * 2);
        av[0] = t1.x; av[1] = t1.y;
        float2 t2 = *reinterpret_cast<const float2*>(bias + lane * 2);
        bv[0] = t2.x; bv[1] = t2.y;
    }

    float mh = -INFINITY, ssum = 0.f;
    float acc[VPL];
    #pragma unroll
    for (int j = 0; j < VPL; ++j) acc[j] = 0.f;

    int e0 = g_off[w], e1 = g_off[w + 1];
    for (int e = e0; e < e1; ++e) {
        int s = g_srcs[e];
        float xv[VPL];
        if (VPL == 4) {
            float4 t = *reinterpret_cast<const float4*>(g_xl + (size_t)s * F + lane * 4);
            xv[0] = t.x; xv[1] = t.y; xv[2] = t.z; xv[3] = t.w;
        } else {
            float2 t = *reinterpret_cast<const float2*>(g_xl + (size_t)s * F + lane * 2);
            xv[0] = t.x; xv[1] = t.y;
        }
        float p = 0.f;
        #pragma unroll
        for (int j = 0; j < VPL; ++j) {
            float m  = xv[j] + xrv[j];
            float lr = (m > 0.f) ? m : 0.2f * m;
            p = fmaf(av[j], lr, p);
        }
        #pragma unroll
        for (int o = 1; o < GR; o <<= 1) p += __shfl_xor_sync(0xffffffffu, p, o);
        float nm    = fmaxf(mh, p);
        float scale = __expf(mh - nm);
        float wgt   = __expf(p - nm);
        ssum = ssum * scale + wgt;
        #pragma unroll
        for (int j = 0; j < VPL; ++j) acc[j] = fmaf(acc[j], scale, wgt * xv[j]);
        mh = nm;
    }
    float inv = 1.f / ssum;
    float o_[VPL];
    #pragma unroll
    for (int j = 0; j < VPL; ++j) {
        float v = fmaf(acc[j], inv, bv[j]);
        if (DOELU) v = (v > 0.f) ? v : expm1f(v);
        o_[j] = v;
    }
    if constexpr (WB16) {
        float r0, r1, r2, r3;
        uint32_t h01 = pack_bf16_hi(o_[0], o_[1], r0, r1);
        uint32_t h23 = pack_bf16_hi(o_[2], o_[3], r2, r3);
        size_t off = (size_t)w * 128 + lane * 4;
        *reinterpret_cast<uint2*>(reinterpret_cast<uint16_t*>(g_ah) + off) = make_uint2(h01, h23);
        *reinterpret_cast<uint2*>(reinterpret_cast<uint16_t*>(g_al) + off) =
            make_uint2(pack_bf16(r0, r1), pack_bf16(r2, r3));
    } else {
        if (VPL == 4) {
            *reinterpret_cast<float4*>(Cext + (size_t)w * F + lane * 4) =
                make_float4(o_[0], o_[1], o_[2], o_[3]);
        } else {
            *reinterpret_cast<float2*>(Cext + (size_t)w * F + lane * 2) =
                make_float2(o_[0], o_[1]);
        }
    }
}

// ---------------- launch: forked graph (CSR branch ∥ prep+GEMM branch) ----------------
extern "C" void kernel_launch(void* const* d_in, const int* in_sizes, int n_in,
                              void* d_out, int out_size) {
    const float* x   = (const float*)d_in[0];
    const int*   ei  = (const int*)d_in[1];
    const float* Wl1 = (const float*)d_in[2];
    const float* Wr1 = (const float*)d_in[3];
    const float* a1  = (const float*)d_in[4];
    const float* b1  = (const float*)d_in[5];
    const float* Wl2 = (const float*)d_in[6];
    const float* Wr2 = (const float*)d_in[7];
    const float* a2  = (const float*)d_in[8];
    const float* b2  = (const float*)d_in[9];
    const float* Wl3 = (const float*)d_in[10];
    const float* Wr3 = (const float*)d_in[11];
    const float* a3  = (const float*)d_in[12];
    const float* b3  = (const float*)d_in[13];
    float* out = (float*)d_out;

    int N = in_sizes[0] / 128;
    int E = in_sizes[1] / 2;

    // one-time host resources (created on the uncaptured correctness call)
    static cudaStream_t s2 = nullptr;
    static cudaEvent_t  evFork = nullptr, evJoin = nullptr;
    if (!s2) {
        cudaStreamCreateWithFlags(&s2, cudaStreamNonBlocking);
        cudaEventCreateWithFlags(&evFork, cudaEventDisableTiming);
        cudaEventCreateWithFlags(&evJoin, cudaEventDisableTiming);
        constexpr int SM128a = (128 + 128) * KP * 2 * 2;
        constexpr int SM64a  = (128 + 64)  * KP * 2 * 2;
        cudaFuncSetAttribute((const void*)sgemm_mma<128>,
                             cudaFuncAttributeMaxDynamicSharedMemorySize, SM128a);
        cudaFuncSetAttribute((const void*)sgemm_mma<64>,
                             cudaFuncAttributeMaxDynamicSharedMemorySize, SM64a);
    }

    constexpr int SM128 = (128 + 128) * KP * 2 * 2;
    constexpr int SM64  = (128 + 64)  * KP * 2 * 2;
    dim3 gGemm(1, (N + 127) / 128, 2);
    int  eBlocks = (N + 7) / 8;
    int  h4 = (E / 4 + 256) / 256;
    int  s4 = ((E + N) / 4 + 256) / 256;

    // fork: CSR branch on s2
    cudaEventRecord(evFork, 0);
    cudaStreamWaitEvent(s2, evFork, 0);
    hist_kernel<<<h4, 256, 0, s2>>>(ei, E);
    scan_kernel<<<1, 1024, 0, s2>>>(N);
    scatter_kernel<<<s4, 256, 0, s2>>>(ei, E, N);
    cudaEventRecord(evJoin, s2);

    // main branch: prep + layer-1 GEMM
    aprep_kernel<<<(N * 32 + 255) / 256, 256>>>(x, N * 32);
    wprep_all<<<(81920 + 255) / 256, 256>>>(Wl1, Wr1, Wl2, Wr2, Wl3, Wr3);
    sgemm_mma<128><<<gGemm, 256, SM128>>>(0, 16384, N);

    // join: edge1 needs CSR + xl/xr
    cudaStreamWaitEvent(0, evJoin, 0);
    edge_kernel<128, 32, true, true><<<eBlocks, 256>>>(a1, b1, nullptr, N);
    sgemm_mma<128><<<gGemm, 256, SM128>>>(32768, 49152, N);
    edge_kernel<128, 32, true, true><<<eBlocks, 256>>>(a2, b2, nullptr, N);
    sgemm_mma<64><<<gGemm, 256, SM64>>>(65536, 73728, N);
    edge_kernel<64, 64, false, false><<<eBlocks, 256>>>(a3, b3, out, N);
}